// round 1
// baseline (speedup 1.0000x reference)
#include <cuda_runtime.h>
#include <math.h>

// ---------------- constants ----------------
#define S_   16
#define N_   256
#define D_   128
#define RR   49
#define K1   2401            // 49*49
#define VSTR 2416            // padded vol row stride (mult of 16)
#define ROWS_T 12288         // 3 levels * 16 * 256

// fmapT offsets
#define FT1_OFF 6291456      // 16*48*64*128
#define FT2_OFF 7864320      // + 16*24*32*128

// ---------------- scratch (static device memory; no allocs) ----------------
__device__ float g_fmapT[8257536];           // all 3 transposed fmaps
__device__ float g_vol[ROWS_T * VSTR];       // 12288 x 2416  (~119 MB)
__device__ float g_h[ROWS_T * 384];
__device__ float g_emb[ROWS_T * 256];

// ---------------- transpose [S,D,H,W] -> [S,H*W,D] ----------------
__global__ void transpose_kernel(const float* __restrict__ src,
                                 float* __restrict__ dst, int HW)
{
    __shared__ float tile[32][33];
    int s   = blockIdx.z;
    int hw0 = blockIdx.x * 32;
    int d0  = blockIdx.y * 32;
    int tx  = threadIdx.x;
    for (int i = threadIdx.y; i < 32; i += 8)
        tile[i][tx] = src[(size_t)(s * D_ + d0 + i) * HW + hw0 + tx];
    __syncthreads();
    for (int i = threadIdx.y; i < 32; i += 8)
        dst[(size_t)(s * HW + hw0 + i) * D_ + d0 + tx] = tile[tx][i];
}

// ---------------- vol kernel: per (s,n) compute 49x49 correlation ----------------
// smem layout (c-major, hw padded to 52 for float4 tiles):
//   sfeat[c][hw], stf[c][ij], stride 52 floats.
__global__ __launch_bounds__(256)
void vol_kernel(const float* __restrict__ fmT, const float* __restrict__ tfs,
                const float* __restrict__ coords, float* __restrict__ vol,
                int H, int W, float invscale, int rowbase)
{
    extern __shared__ float sm[];
    float* sfeat = sm;                 // 128*52
    float* stf   = sm + 128 * 52;      // 128*52

    const int n = blockIdx.x, s = blockIdx.y;
    const int tid = threadIdx.x, lane = tid & 31, wp = tid >> 5;

    // zero smem (covers padded rows 49..51)
    for (int i = tid; i < 2 * 128 * 52; i += 256) sm[i] = 0.f;
    __syncthreads();

    const int sn = s * N_ + n;
    const float cx = coords[sn * 2 + 0] * invscale;
    const float cy = coords[sn * 2 + 1] * invscale;
    const float fxx = floorf(cx), fyy = floorf(cy);
    const int   ix0 = (int)fxx,   iy0 = (int)fyy;
    const float fx = cx - fxx,    fy = cy - fyy;
    const float w00 = (1.f - fx) * (1.f - fy);
    const float w01 = fx * (1.f - fy);
    const float w10 = (1.f - fx) * fy;
    const float w11 = fx * fy;
    const int HWl = H * W;
    const float* base = fmT + (size_t)s * HWl * D_;

    // gather feat: warp per point, lanes over channels (coalesced 512B rows)
    for (int hw = wp; hw < RR; hw += 8) {
        const int h = hw / 7, w = hw % 7;
        const int xi = ix0 + w - 3, yi = iy0 + h - 3;
        const bool vy0 = (yi >= 0) && (yi < H);
        const bool vy1 = (yi + 1 >= 0) && (yi + 1 < H);
        const bool vx0 = (xi >= 0) && (xi < W);
        const bool vx1 = (xi + 1 >= 0) && (xi + 1 < W);
        const float* p00 = base + ((long)yi * W + xi) * D_;
        const float* p01 = p00 + D_;
        const float* p10 = p00 + (long)W * D_;
        const float* p11 = p10 + D_;
        #pragma unroll
        for (int cc = 0; cc < 4; cc++) {
            const int c = lane + 32 * cc;
            float v = 0.f;
            if (vy0 && vx0) v += w00 * p00[c];
            if (vy0 && vx1) v += w01 * p01[c];
            if (vy1 && vx0) v += w10 * p10[c];
            if (vy1 && vx1) v += w11 * p11[c];
            sfeat[c * 52 + hw] = v;
        }
    }
    // load tf: tfs[(ij*256 + n)*128 + c]
    for (int ij = wp; ij < RR; ij += 8) {
        const float* tp = tfs + ((long)ij * N_ + n) * D_;
        #pragma unroll
        for (int cc = 0; cc < 4; cc++) {
            const int c = lane + 32 * cc;
            stf[c * 52 + ij] = tp[c];
        }
    }
    __syncthreads();

    float* vrow = vol + (size_t)(rowbase + sn) * VSTR;
    // zero pad columns 2401..2415 so GEMM can read unguarded
    if (tid < VSTR - K1) vrow[K1 + tid] = 0.f;

    const int ty = tid >> 4, tx = tid & 15;
    if (ty < 13 && tx < 13) {
        float acc[4][4];
        #pragma unroll
        for (int i = 0; i < 4; i++)
            #pragma unroll
            for (int j = 0; j < 4; j++) acc[i][j] = 0.f;

        #pragma unroll 4
        for (int c = 0; c < D_; c++) {
            float4 a = *(float4*)&sfeat[c * 52 + ty * 4];
            float4 b = *(float4*)&stf[c * 52 + tx * 4];
            float av[4] = {a.x, a.y, a.z, a.w};
            float bv[4] = {b.x, b.y, b.z, b.w};
            #pragma unroll
            for (int i = 0; i < 4; i++)
                #pragma unroll
                for (int j = 0; j < 4; j++)
                    acc[i][j] += av[i] * bv[j];
        }
        #pragma unroll
        for (int i = 0; i < 4; i++) {
            const int hw = ty * 4 + i;
            if (hw < RR) {
                #pragma unroll
                for (int j = 0; j < 4; j++) {
                    const int ij = tx * 4 + j;
                    if (ij < RR) vrow[hw * RR + ij] = acc[i][j];
                }
            }
        }
    }
}

// ---------------- canonical 128x128x8 fp32 SGEMM, 8x8 thread tiles ----------------
__device__ __forceinline__ float gelu_exact(float v)
{
    return 0.5f * v * (1.f + erff(v * 0.7071067811865475f));
}

template <bool GELU>
__global__ __launch_bounds__(256)
void sgemm_kernel(const float* __restrict__ A, int lda,
                  const float* __restrict__ B, int ldb,
                  const float* __restrict__ bias,
                  float* __restrict__ C, int ldc,
                  int K, int Kvalid)
{
    __shared__ float As[8 * 128];
    __shared__ float Bs[8 * 128];
    const int tid = threadIdx.x;
    const int m0 = blockIdx.y * 128, n0 = blockIdx.x * 128;
    const int arow = tid >> 1, acol = (tid & 1) * 4;
    const int brow = tid >> 5, bcol = (tid & 31) * 4;
    const int ty = tid >> 4, tx = tid & 15;

    float acc[8][8];
    #pragma unroll
    for (int i = 0; i < 8; i++)
        #pragma unroll
        for (int j = 0; j < 8; j++) acc[i][j] = 0.f;

    for (int k0 = 0; k0 < K; k0 += 8) {
        float4 av = *(const float4*)(A + (size_t)(m0 + arow) * lda + k0 + acol);
        float4 bv = make_float4(0.f, 0.f, 0.f, 0.f);
        if (k0 + brow < Kvalid)
            bv = *(const float4*)(B + (size_t)(k0 + brow) * ldb + n0 + bcol);
        __syncthreads();
        As[(acol + 0) * 128 + arow] = av.x;
        As[(acol + 1) * 128 + arow] = av.y;
        As[(acol + 2) * 128 + arow] = av.z;
        As[(acol + 3) * 128 + arow] = av.w;
        *(float4*)&Bs[brow * 128 + bcol] = bv;
        __syncthreads();
        #pragma unroll
        for (int kk = 0; kk < 8; kk++) {
            float4 a0 = *(float4*)&As[kk * 128 + ty * 8];
            float4 a1 = *(float4*)&As[kk * 128 + ty * 8 + 4];
            float4 b0 = *(float4*)&Bs[kk * 128 + tx * 8];
            float4 b1 = *(float4*)&Bs[kk * 128 + tx * 8 + 4];
            float a[8] = {a0.x, a0.y, a0.z, a0.w, a1.x, a1.y, a1.z, a1.w};
            float b[8] = {b0.x, b0.y, b0.z, b0.w, b1.x, b1.y, b1.z, b1.w};
            #pragma unroll
            for (int i = 0; i < 8; i++)
                #pragma unroll
                for (int j = 0; j < 8; j++)
                    acc[i][j] += a[i] * b[j];
        }
    }

    #pragma unroll
    for (int i = 0; i < 8; i++) {
        const int m = m0 + ty * 8 + i;
        float vv[8];
        #pragma unroll
        for (int j = 0; j < 8; j++) {
            float v = acc[i][j] + bias[n0 + tx * 8 + j];
            if (GELU) v = gelu_exact(v);
            vv[j] = v;
        }
        float* op = C + (size_t)m * ldc + n0 + tx * 8;
        *(float4*)op       = make_float4(vv[0], vv[1], vv[2], vv[3]);
        *((float4*)op + 1) = make_float4(vv[4], vv[5], vv[6], vv[7]);
    }
}

// ---------------- final assembly: concat + posenc + time embedding ----------------
__global__ void assemble_kernel(const float* __restrict__ emb,
                                const float* __restrict__ coords,
                                const float* __restrict__ vis,
                                const float* __restrict__ conf,
                                float* __restrict__ out)
{
    const int n = blockIdx.x, s = blockIdx.y;
    const int sn = s * N_ + n;

    float rfx = 0.f, rfy = 0.f, rbx = 0.f, rby = 0.f;
    const float cx = coords[sn * 2], cy = coords[sn * 2 + 1];
    if (s < S_ - 1) {
        rfx = cx - coords[((s + 1) * N_ + n) * 2];
        rfy = cy - coords[((s + 1) * N_ + n) * 2 + 1];
    }
    if (s > 0) {
        rbx = cx - coords[((s - 1) * N_ + n) * 2];
        rby = cy - coords[((s - 1) * N_ + n) * 2 + 1];
    }
    float p4[4];
    p4[0] = rfx / 64.f;  // MODEL_RES[1]/STRIDE = 512/8
    p4[1] = rfy / 48.f;  // 384/8
    p4[2] = rbx / 64.f;
    p4[3] = rby / 48.f;

    float* orow = out + (size_t)(n * S_ + s) * 854;
    for (int f = threadIdx.x; f < 854; f += 256) {
        float v;
        if (f == 0)      v = vis[sn];
        else if (f == 1) v = conf[sn];
        else if (f < 770) {
            const int lev = (f - 2) >> 8;
            const int c   = (f - 2) & 255;
            v = emb[((size_t)(lev * 4096 + sn)) * 256 + c];
        } else {
            const int j = f - 770;
            if (j < 4) v = p4[j];
            else if (j < 44) {
                const int i = (j - 4) >> 2, q = (j - 4) & 3;
                v = sinf(exp2f((float)i) * p4[q]);
            } else {
                const int i = (j - 44) >> 2, q = (j - 44) & 3;
                v = sinf(exp2f((float)i) * p4[q] + 1.5707963267948966f);
            }
        }
        // sincos time embedding, d=854, d/2=427
        const int i2 = (f < 427) ? f : f - 427;
        const float omega = expf(-9.210340371976184f * (float)i2 / 427.0f); // 10000^{-i/427}
        const float ang = (float)s * omega;
        v += (f < 427) ? sinf(ang) : cosf(ang);
        orow[f] = v;
    }
}

// ---------------- launch ----------------
extern "C" void kernel_launch(void* const* d_in, const int* in_sizes, int n_in,
                              void* d_out, int out_size)
{
    (void)in_sizes; (void)n_in; (void)out_size;
    const float* fm0    = (const float*)d_in[0];
    const float* fm1    = (const float*)d_in[1];
    const float* fm2    = (const float*)d_in[2];
    const float* coords = (const float*)d_in[3];
    const float* tf0    = (const float*)d_in[4];
    const float* tf1    = (const float*)d_in[5];
    const float* tf2    = (const float*)d_in[6];
    const float* vis    = (const float*)d_in[7];
    const float* conf   = (const float*)d_in[8];
    const float* W1     = (const float*)d_in[9];
    const float* b1     = (const float*)d_in[10];
    const float* W2     = (const float*)d_in[11];
    const float* W2b    = (const float*)d_in[12];
    float* out = (float*)d_out;

    float *fT, *vol, *hbuf, *ebuf;
    cudaGetSymbolAddress((void**)&fT,   g_fmapT);
    cudaGetSymbolAddress((void**)&vol,  g_vol);
    cudaGetSymbolAddress((void**)&hbuf, g_h);
    cudaGetSymbolAddress((void**)&ebuf, g_emb);

    const int VOL_SMEM = 2 * 128 * 52 * 4;  // 53248 > 48K default
    cudaFuncSetAttribute(vol_kernel, cudaFuncAttributeMaxDynamicSharedMemorySize, VOL_SMEM);

    dim3 tb(32, 8);
    transpose_kernel<<<dim3(3072 / 32, 4, 16), tb>>>(fm0, fT, 3072);
    transpose_kernel<<<dim3(768 / 32, 4, 16),  tb>>>(fm1, fT + FT1_OFF, 768);
    transpose_kernel<<<dim3(192 / 32, 4, 16),  tb>>>(fm2, fT + FT2_OFF, 192);

    dim3 vg(N_, S_);
    vol_kernel<<<vg, 256, VOL_SMEM>>>(fT,           tf0, coords, vol, 48, 64, 1.0f,  0);
    vol_kernel<<<vg, 256, VOL_SMEM>>>(fT + FT1_OFF, tf1, coords, vol, 24, 32, 0.5f,  4096);
    vol_kernel<<<vg, 256, VOL_SMEM>>>(fT + FT2_OFF, tf2, coords, vol, 12, 16, 0.25f, 8192);

    sgemm_kernel<true ><<<dim3(3, 96), 256>>>(vol,  VSTR, W1, 384, b1,  hbuf, 384, VSTR, K1);
    sgemm_kernel<false><<<dim3(2, 96), 256>>>(hbuf, 384,  W2, 256, W2b, ebuf, 256, 384,  384);

    assemble_kernel<<<dim3(N_, S_), 256>>>(ebuf, coords, vis, conf, out);
}

// round 2
// speedup vs baseline: 1.4638x; 1.4638x over previous
#include <cuda_runtime.h>
#include <math.h>
#include <stdint.h>

// ---------------- constants ----------------
#define S_   16
#define N_   256
#define D_   128
#define RR   49
#define K1   2401            // 49*49
#define VSTR 2416            // padded vol row stride (mult of 16)
#define ROWS_T 12288         // 3 levels * 16 * 256

// fmapT offsets
#define FT1_OFF 6291456      // 16*48*64*128
#define FT2_OFF 7864320      // + 16*24*32*128

// ---------------- scratch (static device memory; no allocs) ----------------
__device__ float g_fmapT[8257536];           // all 3 transposed fmaps
__device__ float g_vol[ROWS_T * VSTR];       // 12288 x 2416  (~119 MB)
__device__ float g_h[ROWS_T * 384];
__device__ float g_emb[ROWS_T * 256];

// ---------------- transpose [S,D,H,W] -> [S,H*W,D] ----------------
__global__ void transpose_kernel(const float* __restrict__ src,
                                 float* __restrict__ dst, int HW)
{
    __shared__ float tile[32][33];
    int s   = blockIdx.z;
    int hw0 = blockIdx.x * 32;
    int d0  = blockIdx.y * 32;
    int tx  = threadIdx.x;
    for (int i = threadIdx.y; i < 32; i += 8)
        tile[i][tx] = src[(size_t)(s * D_ + d0 + i) * HW + hw0 + tx];
    __syncthreads();
    for (int i = threadIdx.y; i < 32; i += 8)
        dst[(size_t)(s * HW + hw0 + i) * D_ + d0 + tx] = tile[tx][i];
}

// ---------------- vol kernel: per (level,s,n) compute 49x49 correlation -------
__global__ __launch_bounds__(256)
void vol_kernel(const float* __restrict__ fmTbase,
                const float* __restrict__ tf0,
                const float* __restrict__ tf1,
                const float* __restrict__ tf2,
                const float* __restrict__ coords, float* __restrict__ vol)
{
    extern __shared__ float sm[];
    float* sfeat = sm;                 // 128*52
    float* stf   = sm + 128 * 52;      // 128*52

    const int n = blockIdx.x, s = blockIdx.y, lev = blockIdx.z;
    const int tid = threadIdx.x, lane = tid & 31, wp = tid >> 5;

    int H, W, off;
    float invscale;
    const float* tfs;
    if (lev == 0)      { H = 48; W = 64; off = 0;       invscale = 1.0f;  tfs = tf0; }
    else if (lev == 1) { H = 24; W = 32; off = FT1_OFF; invscale = 0.5f;  tfs = tf1; }
    else               { H = 12; W = 16; off = FT2_OFF; invscale = 0.25f; tfs = tf2; }

    // zero smem (covers padded rows 49..51)
    for (int i = tid; i < 2 * 128 * 52; i += 256) sm[i] = 0.f;
    __syncthreads();

    const int sn = s * N_ + n;
    const float cx = coords[sn * 2 + 0] * invscale;
    const float cy = coords[sn * 2 + 1] * invscale;
    const float fxx = floorf(cx), fyy = floorf(cy);
    const int   ix0 = (int)fxx,   iy0 = (int)fyy;
    const float fx = cx - fxx,    fy = cy - fyy;
    const float w00 = (1.f - fx) * (1.f - fy);
    const float w01 = fx * (1.f - fy);
    const float w10 = (1.f - fx) * fy;
    const float w11 = fx * fy;
    const float* base = fmTbase + off + (size_t)s * H * W * D_;

    // gather feat: warp per point, lanes over channels (coalesced 512B rows)
    for (int hw = wp; hw < RR; hw += 8) {
        const int h = hw / 7, w = hw % 7;
        const int xi = ix0 + w - 3, yi = iy0 + h - 3;
        const bool vy0 = (yi >= 0) && (yi < H);
        const bool vy1 = (yi + 1 >= 0) && (yi + 1 < H);
        const bool vx0 = (xi >= 0) && (xi < W);
        const bool vx1 = (xi + 1 >= 0) && (xi + 1 < W);
        const float* p00 = base + ((long)yi * W + xi) * D_;
        const float* p01 = p00 + D_;
        const float* p10 = p00 + (long)W * D_;
        const float* p11 = p10 + D_;
        #pragma unroll
        for (int cc = 0; cc < 4; cc++) {
            const int c = lane + 32 * cc;
            float v = 0.f;
            if (vy0 && vx0) v += w00 * p00[c];
            if (vy0 && vx1) v += w01 * p01[c];
            if (vy1 && vx0) v += w10 * p10[c];
            if (vy1 && vx1) v += w11 * p11[c];
            sfeat[c * 52 + hw] = v;
        }
    }
    // load tf: tfs[(ij*256 + n)*128 + c]
    for (int ij = wp; ij < RR; ij += 8) {
        const float* tp = tfs + ((long)ij * N_ + n) * D_;
        #pragma unroll
        for (int cc = 0; cc < 4; cc++) {
            const int c = lane + 32 * cc;
            stf[c * 52 + ij] = tp[c];
        }
    }
    __syncthreads();

    float* vrow = vol + (size_t)(lev * 4096 + sn) * VSTR;
    // zero pad columns 2401..2415 so GEMM can read unguarded
    if (tid < VSTR - K1) vrow[K1 + tid] = 0.f;

    const int ty = tid >> 4, tx = tid & 15;
    if (ty < 13 && tx < 13) {
        float acc[4][4];
        #pragma unroll
        for (int i = 0; i < 4; i++)
            #pragma unroll
            for (int j = 0; j < 4; j++) acc[i][j] = 0.f;

        #pragma unroll 4
        for (int c = 0; c < D_; c++) {
            float4 a = *(float4*)&sfeat[c * 52 + ty * 4];
            float4 b = *(float4*)&stf[c * 52 + tx * 4];
            float av[4] = {a.x, a.y, a.z, a.w};
            float bv[4] = {b.x, b.y, b.z, b.w};
            #pragma unroll
            for (int i = 0; i < 4; i++)
                #pragma unroll
                for (int j = 0; j < 4; j++)
                    acc[i][j] += av[i] * bv[j];
        }
        #pragma unroll
        for (int i = 0; i < 4; i++) {
            const int hw = ty * 4 + i;
            if (hw < RR) {
                #pragma unroll
                for (int j = 0; j < 4; j++) {
                    const int ij = tx * 4 + j;
                    if (ij < RR) vrow[hw * RR + ij] = acc[i][j];
                }
            }
        }
    }
}

// ---------------- tf32 tensor-core GEMM, 128x128 tile, m16n8k8 mma -----------
__device__ __forceinline__ float gelu_exact(float v)
{
    return 0.5f * v * (1.f + erff(v * 0.7071067811865475f));
}

__device__ __forceinline__ uint32_t f2tf32(float f)
{
    uint32_t r;
    asm("cvt.rna.tf32.f32 %0, %1;" : "=r"(r) : "f"(f));
    return r;
}

__device__ __forceinline__ void mma_tf32(float* c, const uint32_t* a, const uint32_t* b)
{
    asm volatile(
        "mma.sync.aligned.m16n8k8.row.col.f32.tf32.tf32.f32 "
        "{%0,%1,%2,%3}, {%4,%5,%6,%7}, {%8,%9}, {%0,%1,%2,%3};"
        : "+f"(c[0]), "+f"(c[1]), "+f"(c[2]), "+f"(c[3])
        : "r"(a[0]), "r"(a[1]), "r"(a[2]), "r"(a[3]), "r"(b[0]), "r"(b[1]));
}

#define SST 136  // smem row stride (conflict-free for frag pattern)

template <bool GELU>
__global__ __launch_bounds__(256)
void tf32_gemm(const float* __restrict__ A, int lda,
               const float* __restrict__ B, int ldb,
               const float* __restrict__ bias,
               float* __restrict__ C, int ldc,
               int K, int Kvalid)
{
    __shared__ uint32_t As[16][SST];
    __shared__ uint32_t Bs[16][SST];

    const int tid  = threadIdx.x;
    const int lane = tid & 31;
    const int warp = tid >> 5;
    const int m0 = blockIdx.y * 128, n0 = blockIdx.x * 128;
    const int wm = (warp >> 2) * 64, wn = (warp & 3) * 32;

    // staging assignments
    const int am  = tid & 127;           // A row within tile
    const int akc = (tid >> 7) * 2;      // first of two k-float4s
    const int bk  = tid >> 5;            // B k row 0..7 (and +8)
    const int bn  = (tid & 31) * 4;      // B col

    float acc[4][4][4];
    #pragma unroll
    for (int mi = 0; mi < 4; mi++)
        #pragma unroll
        for (int ni = 0; ni < 4; ni++)
            #pragma unroll
            for (int q = 0; q < 4; q++) acc[mi][ni][q] = 0.f;

    for (int k0 = 0; k0 < K; k0 += 16) {
        // stage A (transpose to [k][m], convert to tf32)
        #pragma unroll
        for (int q = 0; q < 2; q++) {
            const int kc = akc + q;
            float4 v = *(const float4*)(A + (size_t)(m0 + am) * lda + k0 + kc * 4);
            As[kc * 4 + 0][am] = f2tf32(v.x);
            As[kc * 4 + 1][am] = f2tf32(v.y);
            As[kc * 4 + 2][am] = f2tf32(v.z);
            As[kc * 4 + 3][am] = f2tf32(v.w);
        }
        // stage B ([k][n], convert)
        #pragma unroll
        for (int q = 0; q < 2; q++) {
            const int kr = bk + 8 * q;
            float4 v = make_float4(0.f, 0.f, 0.f, 0.f);
            if (k0 + kr < Kvalid)
                v = *(const float4*)(B + (size_t)(k0 + kr) * ldb + n0 + bn);
            Bs[kr][bn + 0] = f2tf32(v.x);
            Bs[kr][bn + 1] = f2tf32(v.y);
            Bs[kr][bn + 2] = f2tf32(v.z);
            Bs[kr][bn + 3] = f2tf32(v.w);
        }
        __syncthreads();

        #pragma unroll
        for (int kt = 0; kt < 2; kt++) {
            const int kb = kt * 8;
            const int kl = kb + (lane & 3);
            const int rg = lane >> 2;
            uint32_t af[4][4], bf[4][2];
            #pragma unroll
            for (int mi = 0; mi < 4; mi++) {
                const int mb = wm + mi * 16 + rg;
                af[mi][0] = As[kl][mb];
                af[mi][1] = As[kl][mb + 8];
                af[mi][2] = As[kl + 4][mb];
                af[mi][3] = As[kl + 4][mb + 8];
            }
            #pragma unroll
            for (int ni = 0; ni < 4; ni++) {
                const int nb = wn + ni * 8 + rg;
                bf[ni][0] = Bs[kl][nb];
                bf[ni][1] = Bs[kl + 4][nb];
            }
            #pragma unroll
            for (int mi = 0; mi < 4; mi++)
                #pragma unroll
                for (int ni = 0; ni < 4; ni++)
                    mma_tf32(acc[mi][ni], af[mi], bf[ni]);
        }
        __syncthreads();
    }

    // epilogue: bias (+gelu), write C
    #pragma unroll
    for (int mi = 0; mi < 4; mi++) {
        const int r0 = m0 + wm + mi * 16 + (lane >> 2);
        #pragma unroll
        for (int ni = 0; ni < 4; ni++) {
            const int c0 = n0 + wn + ni * 8 + 2 * (lane & 3);
            const float bb0 = bias[c0], bb1 = bias[c0 + 1];
            float v0 = acc[mi][ni][0] + bb0;
            float v1 = acc[mi][ni][1] + bb1;
            float v2 = acc[mi][ni][2] + bb0;
            float v3 = acc[mi][ni][3] + bb1;
            if (GELU) {
                v0 = gelu_exact(v0); v1 = gelu_exact(v1);
                v2 = gelu_exact(v2); v3 = gelu_exact(v3);
            }
            *(float2*)(C + (size_t)r0 * ldc + c0)       = make_float2(v0, v1);
            *(float2*)(C + (size_t)(r0 + 8) * ldc + c0) = make_float2(v2, v3);
        }
    }
}

// ---------------- final assembly: concat + posenc + time embedding ----------------
__global__ void assemble_kernel(const float* __restrict__ emb,
                                const float* __restrict__ coords,
                                const float* __restrict__ vis,
                                const float* __restrict__ conf,
                                float* __restrict__ out)
{
    const int n = blockIdx.x, s = blockIdx.y;
    const int sn = s * N_ + n;

    float rfx = 0.f, rfy = 0.f, rbx = 0.f, rby = 0.f;
    const float cx = coords[sn * 2], cy = coords[sn * 2 + 1];
    if (s < S_ - 1) {
        rfx = cx - coords[((s + 1) * N_ + n) * 2];
        rfy = cy - coords[((s + 1) * N_ + n) * 2 + 1];
    }
    if (s > 0) {
        rbx = cx - coords[((s - 1) * N_ + n) * 2];
        rby = cy - coords[((s - 1) * N_ + n) * 2 + 1];
    }
    float p4[4];
    p4[0] = rfx / 64.f;
    p4[1] = rfy / 48.f;
    p4[2] = rbx / 64.f;
    p4[3] = rby / 48.f;

    float* orow = out + (size_t)(n * S_ + s) * 854;
    for (int f = threadIdx.x; f < 854; f += 256) {
        float v;
        if (f == 0)      v = vis[sn];
        else if (f == 1) v = conf[sn];
        else if (f < 770) {
            const int lev = (f - 2) >> 8;
            const int c   = (f - 2) & 255;
            v = emb[((size_t)(lev * 4096 + sn)) * 256 + c];
        } else {
            const int j = f - 770;
            if (j < 4) v = p4[j];
            else if (j < 44) {
                const int i = (j - 4) >> 2, q = (j - 4) & 3;
                v = sinf(exp2f((float)i) * p4[q]);
            } else {
                const int i = (j - 44) >> 2, q = (j - 44) & 3;
                v = sinf(exp2f((float)i) * p4[q] + 1.5707963267948966f);
            }
        }
        const int i2 = (f < 427) ? f : f - 427;
        const float omega = expf(-9.210340371976184f * (float)i2 / 427.0f);
        const float ang = (float)s * omega;
        v += (f < 427) ? sinf(ang) : cosf(ang);
        orow[f] = v;
    }
}

// ---------------- launch ----------------
extern "C" void kernel_launch(void* const* d_in, const int* in_sizes, int n_in,
                              void* d_out, int out_size)
{
    (void)in_sizes; (void)n_in; (void)out_size;
    const float* fm0    = (const float*)d_in[0];
    const float* fm1    = (const float*)d_in[1];
    const float* fm2    = (const float*)d_in[2];
    const float* coords = (const float*)d_in[3];
    const float* tf0    = (const float*)d_in[4];
    const float* tf1    = (const float*)d_in[5];
    const float* tf2    = (const float*)d_in[6];
    const float* vis    = (const float*)d_in[7];
    const float* conf   = (const float*)d_in[8];
    const float* W1     = (const float*)d_in[9];
    const float* b1     = (const float*)d_in[10];
    const float* W2     = (const float*)d_in[11];
    const float* W2b    = (const float*)d_in[12];
    float* out = (float*)d_out;

    float *fT, *vol, *hbuf, *ebuf;
    cudaGetSymbolAddress((void**)&fT,   g_fmapT);
    cudaGetSymbolAddress((void**)&vol,  g_vol);
    cudaGetSymbolAddress((void**)&hbuf, g_h);
    cudaGetSymbolAddress((void**)&ebuf, g_emb);

    const int VOL_SMEM = 2 * 128 * 52 * 4;
    cudaFuncSetAttribute(vol_kernel, cudaFuncAttributeMaxDynamicSharedMemorySize, VOL_SMEM);

    dim3 tb(32, 8);
    transpose_kernel<<<dim3(3072 / 32, 4, 16), tb>>>(fm0, fT, 3072);
    transpose_kernel<<<dim3(768 / 32, 4, 16),  tb>>>(fm1, fT + FT1_OFF, 768);
    transpose_kernel<<<dim3(192 / 32, 4, 16),  tb>>>(fm2, fT + FT2_OFF, 192);

    vol_kernel<<<dim3(N_, S_, 3), 256, VOL_SMEM>>>(fT, tf0, tf1, tf2, coords, vol);

    tf32_gemm<true ><<<dim3(3, 96), 256>>>(vol,  VSTR, W1, 384, b1,  hbuf, 384, VSTR, K1);
    tf32_gemm<false><<<dim3(2, 96), 256>>>(hbuf, 384,  W2, 256, W2b, ebuf, 256, 384,  384);

    assemble_kernel<<<dim3(N_, S_), 256>>>(ebuf, coords, vis, conf, out);
}

// round 4
// speedup vs baseline: 2.1869x; 1.4940x over previous
#include <cuda_runtime.h>
#include <cuda_bf16.h>
#include <math.h>
#include <stdint.h>

// ---------------- constants ----------------
#define S_   16
#define N_   256
#define D_   128
#define RR   49
#define K1   2401            // 49*49
#define VSTR 2416            // padded vol row stride (mult of 16)
#define ROWS_T 12288         // 3 levels * 16 * 256

// fmapT offsets
#define FT1_OFF 6291456      // 16*48*64*128
#define FT2_OFF 7864320      // + 16*24*32*128

// ---------------- scratch (static device memory; no allocs) ----------------
__device__ float g_fmapT[8257536];           // all 3 transposed fmaps
__device__ float g_vol[ROWS_T * VSTR];       // 12288 x 2416
__device__ float g_h[ROWS_T * 384];
__device__ float g_emb[ROWS_T * 256];
__device__ float g_w1r[K1 * 384];            // tf32-rounded W1
__device__ float g_w2r[384 * 256];           // tf32-rounded W2

// ---------------- helpers ----------------
__device__ __forceinline__ uint32_t f2tf32(float f)
{
    uint32_t r;
    asm("cvt.rna.tf32.f32 %0, %1;" : "=r"(r) : "f"(f));
    return r;
}

__device__ __forceinline__ float tf32r(float f) { return __uint_as_float(f2tf32(f)); }

__device__ __forceinline__ uint32_t pack_bf2(float a, float b)
{
    __nv_bfloat162 p = __floats2bfloat162_rn(a, b);
    return *(uint32_t*)&p;
}

__device__ __forceinline__ void mma_tf32(float* c, const uint32_t* a, const uint32_t* b)
{
    asm volatile(
        "mma.sync.aligned.m16n8k8.row.col.f32.tf32.tf32.f32 "
        "{%0,%1,%2,%3}, {%4,%5,%6,%7}, {%8,%9}, {%0,%1,%2,%3};"
        : "+f"(c[0]), "+f"(c[1]), "+f"(c[2]), "+f"(c[3])
        : "r"(a[0]), "r"(a[1]), "r"(a[2]), "r"(a[3]), "r"(b[0]), "r"(b[1]));
}

__device__ __forceinline__ void mma_bf16(float* c, const uint32_t* a, const uint32_t* b)
{
    asm volatile(
        "mma.sync.aligned.m16n8k16.row.col.f32.bf16.bf16.f32 "
        "{%0,%1,%2,%3}, {%4,%5,%6,%7}, {%8,%9}, {%0,%1,%2,%3};"
        : "+f"(c[0]), "+f"(c[1]), "+f"(c[2]), "+f"(c[3])
        : "r"(a[0]), "r"(a[1]), "r"(a[2]), "r"(a[3]), "r"(b[0]), "r"(b[1]));
}

__device__ __forceinline__ void cpa16(uint32_t dst, const void* src, bool pred)
{
    asm volatile("cp.async.ca.shared.global [%0], [%1], 16, %2;"
                 :: "r"(dst), "l"(src), "r"(pred ? 16 : 0) : "memory");
}
__device__ __forceinline__ void cpa_commit() { asm volatile("cp.async.commit_group;" ::: "memory"); }
__device__ __forceinline__ void cpa_wait0()  { asm volatile("cp.async.wait_group 0;" ::: "memory"); }
__device__ __forceinline__ void cpa_wait1()  { asm volatile("cp.async.wait_group 1;" ::: "memory"); }

// ---------------- transpose [S,D,H,W] -> [S,H*W,D] ----------------
__global__ void transpose_kernel(const float* __restrict__ src,
                                 float* __restrict__ dst, int HW)
{
    __shared__ float tile[32][33];
    int s   = blockIdx.z;
    int hw0 = blockIdx.x * 32;
    int d0  = blockIdx.y * 32;
    int tx  = threadIdx.x;
    for (int i = threadIdx.y; i < 32; i += 8)
        tile[i][tx] = src[(size_t)(s * D_ + d0 + i) * HW + hw0 + tx];
    __syncthreads();
    for (int i = threadIdx.y; i < 32; i += 8)
        dst[(size_t)(s * HW + hw0 + i) * D_ + d0 + tx] = tile[tx][i];
}

// ---------------- round weights to tf32-representable fp32 ----------------
__global__ void round_tf32_kernel(const float* __restrict__ src,
                                  float* __restrict__ dst, int n)
{
    int i = blockIdx.x * 256 + threadIdx.x;
    if (i < n) dst[i] = tf32r(src[i]);
}

// ---------------- vol kernel: tensor-core 3xBF16 split correlation ----------
// A (feat): [m=64 pad][kp 0..63] bf16x2 words, stride 68
// B (tf):   [n=56 pad][kp 0..63] bf16x2 words, stride 68
#define VA_W 68
#define VA_SZ (64 * VA_W)   // 4352 words
#define VB_SZ (56 * VA_W)   // 3808 words
#define VOL_SMEM ((2 * VA_SZ + 2 * VB_SZ) * 4)   // 65280 B

__global__ __launch_bounds__(256)
void vol_kernel(const float* __restrict__ fmTbase,
                const float* __restrict__ tf0,
                const float* __restrict__ tf1,
                const float* __restrict__ tf2,
                const float* __restrict__ coords, float* __restrict__ vol)
{
    extern __shared__ uint32_t smv[];
    uint32_t* AsH = smv;
    uint32_t* AsL = AsH + VA_SZ;
    uint32_t* BsH = AsL + VA_SZ;
    uint32_t* BsL = BsH + VB_SZ;

    const int n = blockIdx.x, s = blockIdx.y, lev = blockIdx.z;
    const int tid = threadIdx.x, lane = tid & 31, wp = tid >> 5;

    int H, W, off;
    float invscale;
    const float* tfs;
    if (lev == 0)      { H = 48; W = 64; off = 0;       invscale = 1.0f;  tfs = tf0; }
    else if (lev == 1) { H = 24; W = 32; off = FT1_OFF; invscale = 0.5f;  tfs = tf1; }
    else               { H = 12; W = 16; off = FT2_OFF; invscale = 0.25f; tfs = tf2; }

    const int sn = s * N_ + n;
    const float cx = coords[sn * 2 + 0] * invscale;
    const float cy = coords[sn * 2 + 1] * invscale;
    const float fxx = floorf(cx), fyy = floorf(cy);
    const int   ix0 = (int)fxx,   iy0 = (int)fyy;
    const float fx = cx - fxx,    fy = cy - fyy;
    const float w00 = (1.f - fx) * (1.f - fy);
    const float w01 = fx * (1.f - fy);
    const float w10 = (1.f - fx) * fy;
    const float w11 = fx * fy;
    const float* base = fmTbase + off + (size_t)s * H * W * D_;

    // gather feat: warp per point hw; lane owns channel pairs
    for (int hw = wp; hw < RR; hw += 8) {
        const int h = hw / 7, w = hw % 7;
        const int xi = ix0 + w - 3, yi = iy0 + h - 3;
        const bool vy0 = (yi >= 0) && (yi < H);
        const bool vy1 = (yi + 1 >= 0) && (yi + 1 < H);
        const bool vx0 = (xi >= 0) && (xi < W);
        const bool vx1 = (xi + 1 >= 0) && (xi + 1 < W);
        const float* p00 = base + ((long)yi * W + xi) * D_;
        const float* p01 = p00 + D_;
        const float* p10 = p00 + (long)W * D_;
        const float* p11 = p10 + D_;
        #pragma unroll
        for (int cc = 0; cc < 2; cc++) {
            const int c = 2 * lane + 64 * cc;
            float v0 = 0.f, v1 = 0.f;
            if (vy0 && vx0) { float2 t = *(const float2*)(p00 + c); v0 += w00 * t.x; v1 += w00 * t.y; }
            if (vy0 && vx1) { float2 t = *(const float2*)(p01 + c); v0 += w01 * t.x; v1 += w01 * t.y; }
            if (vy1 && vx0) { float2 t = *(const float2*)(p10 + c); v0 += w10 * t.x; v1 += w10 * t.y; }
            if (vy1 && vx1) { float2 t = *(const float2*)(p11 + c); v0 += w11 * t.x; v1 += w11 * t.y; }
            const float h0 = __bfloat162float(__float2bfloat16(v0));
            const float h1 = __bfloat162float(__float2bfloat16(v1));
            const int kp = lane + 32 * cc;
            AsH[hw * VA_W + kp] = pack_bf2(h0, h1);
            AsL[hw * VA_W + kp] = pack_bf2(v0 - h0, v1 - h1);
        }
    }
    // gather tf: warp per ij
    for (int ij = wp; ij < RR; ij += 8) {
        const float* tp = tfs + ((long)ij * N_ + n) * D_;
        #pragma unroll
        for (int cc = 0; cc < 2; cc++) {
            const int c = 2 * lane + 64 * cc;
            float2 t = *(const float2*)(tp + c);
            const float h0 = __bfloat162float(__float2bfloat16(t.x));
            const float h1 = __bfloat162float(__float2bfloat16(t.y));
            const int kp = lane + 32 * cc;
            BsH[ij * VA_W + kp] = pack_bf2(h0, h1);
            BsL[ij * VA_W + kp] = pack_bf2(t.x - h0, t.y - h1);
        }
    }
    __syncthreads();

    float* vrow = vol + (size_t)(lev * 4096 + sn) * VSTR;
    if (tid < VSTR - K1) vrow[K1 + tid] = 0.f;

    // mma: warp -> m tile (warp&3)*16, n half (warp>>2)
    const int wm  = (wp & 3) * 16;
    const int nh  = wp >> 2;
    const int nt0 = nh ? 4 : 0;
    const int ntN = nh ? 3 : 4;
    const int t = lane & 3, g = lane >> 2;

    float acc[4][4];
    #pragma unroll
    for (int i = 0; i < 4; i++)
        #pragma unroll
        for (int q = 0; q < 4; q++) acc[i][q] = 0.f;

    #pragma unroll
    for (int ks = 0; ks < 8; ks++) {
        const int kpb = ks * 8;
        uint32_t ah[4], al[4];
        const int ra = (wm + g) * VA_W + kpb + t;
        const int rb = (wm + g + 8) * VA_W + kpb + t;
        ah[0] = AsH[ra];     ah[1] = AsH[rb];
        ah[2] = AsH[ra + 4]; ah[3] = AsH[rb + 4];
        al[0] = AsL[ra];     al[1] = AsL[rb];
        al[2] = AsL[ra + 4]; al[3] = AsL[rb + 4];
        #pragma unroll
        for (int ni = 0; ni < 4; ni++) {
            if (ni >= ntN) break;
            const int nb = ((nt0 + ni) * 8 + g) * VA_W + kpb + t;
            uint32_t bh[2], bl[2];
            bh[0] = BsH[nb]; bh[1] = BsH[nb + 4];
            bl[0] = BsL[nb]; bl[1] = BsL[nb + 4];
            mma_bf16(acc[ni], ah, bh);
            mma_bf16(acc[ni], ah, bl);
            mma_bf16(acc[ni], al, bh);
        }
    }

    // epilogue: store (tf32-rounded for the downstream GEMM)
    #pragma unroll
    for (int ni = 0; ni < 4; ni++) {
        if (ni >= ntN) break;
        const int col0 = (nt0 + ni) * 8 + 2 * t;
        const int r0 = wm + g, r1 = r0 + 8;
        if (r0 < RR) {
            if (col0 < RR)     vrow[r0 * RR + col0]     = tf32r(acc[ni][0]);
            if (col0 + 1 < RR) vrow[r0 * RR + col0 + 1] = tf32r(acc[ni][1]);
        }
        if (r1 < RR) {
            if (col0 < RR)     vrow[r1 * RR + col0]     = tf32r(acc[ni][2]);
            if (col0 + 1 < RR) vrow[r1 * RR + col0 + 1] = tf32r(acc[ni][3]);
        }
    }
}

// ---------------- pipelined tf32 GEMM, 128x128 tile, cp.async 2-stage -------
__device__ __forceinline__ float gelu_exact(float v)
{
    return 0.5f * v * (1.f + erff(v * 0.7071067811865475f));
}

#define AST 20   // A smem word stride per m row (16 k + pad)
#define BST 136  // B smem word stride per k row (128 n + pad)

template <bool GELU, bool ROUND_OUT>
__global__ __launch_bounds__(256)
void tf32_gemm_pipe(const float* __restrict__ A, int lda,
                    const float* __restrict__ B, int ldb,
                    const float* __restrict__ bias,
                    float* __restrict__ C, int ldc,
                    int K, int Kvalid)
{
    __shared__ float As[2][128 * AST];
    __shared__ float Bs[2][16 * BST];

    const int tid  = threadIdx.x;
    const int lane = tid & 31;
    const int warp = tid >> 5;
    const int m0 = blockIdx.y * 128, n0 = blockIdx.x * 128;
    const int wm = (warp >> 2) * 64, wn = (warp & 3) * 32;
    const int t = lane & 3, g = lane >> 2;

    // cp.async assignments: A needs 128 rows x 16 k = 512 float4 = 2/thread
    const int am = tid >> 1, ak = (tid & 1) * 8;       // A: row 0..127, k-base 0/8
    const int bk = tid >> 5, bnc = (tid & 31) * 4;     // B: k-row, col-quad

    uint32_t sA0, sA1, sB0, sB1;
    {
        uint32_t a = (uint32_t)__cvta_generic_to_shared(&As[0][0]);
        sA0 = a + (am * AST + ak) * 4;
        sA1 = sA0 + 128 * AST * 4;
        uint32_t b = (uint32_t)__cvta_generic_to_shared(&Bs[0][0]);
        sB0 = b + (bk * BST + bnc) * 4;
        sB1 = sB0 + 16 * BST * 4;
    }
    const float* gA = A + (size_t)(m0 + am) * lda + ak;
    const float* gB = B + (size_t)bk * ldb + n0 + bnc;

    float acc[4][4][4];
    #pragma unroll
    for (int mi = 0; mi < 4; mi++)
        #pragma unroll
        for (int ni = 0; ni < 4; ni++)
            #pragma unroll
            for (int q = 0; q < 4; q++) acc[mi][ni][q] = 0.f;

    const int NIT = K / 16;
    // prefetch stage 0
    cpa16(sA0,      gA,     true);
    cpa16(sA0 + 16, gA + 4, true);
    cpa16(sB0, gB, bk < Kvalid);
    cpa16(sB0 + 8 * BST * 4, gB + (size_t)8 * ldb, bk + 8 < Kvalid);
    cpa_commit();

    for (int it = 0; it < NIT; it++) {
        const int cur = it & 1;
        if (it + 1 < NIT) {
            const int k0 = (it + 1) * 16;
            const uint32_t dA = cur ? sA0 : sA1;
            const uint32_t dB = cur ? sB0 : sB1;
            cpa16(dA,      gA + k0,     true);
            cpa16(dA + 16, gA + k0 + 4, true);
            cpa16(dB, gB + (size_t)k0 * ldb, k0 + bk < Kvalid);
            cpa16(dB + 8 * BST * 4, gB + (size_t)(k0 + 8) * ldb, k0 + bk + 8 < Kvalid);
            cpa_commit();
            cpa_wait1();
        } else {
            cpa_wait0();
        }
        __syncthreads();

        const float* Ab = As[cur];
        const float* Bb = Bs[cur];
        #pragma unroll
        for (int kb = 0; kb < 16; kb += 8) {
            uint32_t af[4][4], bf[4][2];
            #pragma unroll
            for (int mi = 0; mi < 4; mi++) {
                const int r = (wm + mi * 16 + g) * AST + kb + t;
                af[mi][0] = __float_as_uint(Ab[r]);
                af[mi][1] = __float_as_uint(Ab[r + 8 * AST]);
                af[mi][2] = __float_as_uint(Ab[r + 4]);
                af[mi][3] = __float_as_uint(Ab[r + 8 * AST + 4]);
            }
            #pragma unroll
            for (int ni = 0; ni < 4; ni++) {
                const int cidx = (kb + t) * BST + wn + ni * 8 + g;
                bf[ni][0] = __float_as_uint(Bb[cidx]);
                bf[ni][1] = __float_as_uint(Bb[cidx + 4 * BST]);
            }
            #pragma unroll
            for (int mi = 0; mi < 4; mi++)
                #pragma unroll
                for (int ni = 0; ni < 4; ni++)
                    mma_tf32(acc[mi][ni], af[mi], bf[ni]);
        }
        __syncthreads();
    }

    // epilogue: bias (+gelu) (+tf32 round), write C
    #pragma unroll
    for (int mi = 0; mi < 4; mi++) {
        const int r0 = m0 + wm + mi * 16 + g;
        #pragma unroll
        for (int ni = 0; ni < 4; ni++) {
            const int c0 = n0 + wn + ni * 8 + 2 * t;
            const float bb0 = bias[c0], bb1 = bias[c0 + 1];
            float v0 = acc[mi][ni][0] + bb0;
            float v1 = acc[mi][ni][1] + bb1;
            float v2 = acc[mi][ni][2] + bb0;
            float v3 = acc[mi][ni][3] + bb1;
            if (GELU) {
                v0 = gelu_exact(v0); v1 = gelu_exact(v1);
                v2 = gelu_exact(v2); v3 = gelu_exact(v3);
            }
            if (ROUND_OUT) {
                v0 = tf32r(v0); v1 = tf32r(v1);
                v2 = tf32r(v2); v3 = tf32r(v3);
            }
            *(float2*)(C + (size_t)r0 * ldc + c0)       = make_float2(v0, v1);
            *(float2*)(C + (size_t)(r0 + 8) * ldc + c0) = make_float2(v2, v3);
        }
    }
}

// ---------------- final assembly: concat + posenc + time embedding ----------------
__global__ void assemble_kernel(const float* __restrict__ emb,
                                const float* __restrict__ coords,
                                const float* __restrict__ vis,
                                const float* __restrict__ conf,
                                float* __restrict__ out)
{
    const int n = blockIdx.x, s = blockIdx.y;
    const int sn = s * N_ + n;

    float rfx = 0.f, rfy = 0.f, rbx = 0.f, rby = 0.f;
    const float cx = coords[sn * 2], cy = coords[sn * 2 + 1];
    if (s < S_ - 1) {
        rfx = cx - coords[((s + 1) * N_ + n) * 2];
        rfy = cy - coords[((s + 1) * N_ + n) * 2 + 1];
    }
    if (s > 0) {
        rbx = cx - coords[((s - 1) * N_ + n) * 2];
        rby = cy - coords[((s - 1) * N_ + n) * 2 + 1];
    }
    float p4[4];
    p4[0] = rfx / 64.f;
    p4[1] = rfy / 48.f;
    p4[2] = rbx / 64.f;
    p4[3] = rby / 48.f;

    float* orow = out + (size_t)(n * S_ + s) * 854;
    for (int f = threadIdx.x; f < 854; f += 256) {
        float v;
        if (f == 0)      v = vis[sn];
        else if (f == 1) v = conf[sn];
        else if (f < 770) {
            const int lev = (f - 2) >> 8;
            const int c   = (f - 2) & 255;
            v = emb[((size_t)(lev * 4096 + sn)) * 256 + c];
        } else {
            const int j = f - 770;
            if (j < 4) v = p4[j];
            else if (j < 44) {
                const int i = (j - 4) >> 2, q = (j - 4) & 3;
                v = sinf(exp2f((float)i) * p4[q]);
            } else {
                const int i = (j - 44) >> 2, q = (j - 44) & 3;
                v = sinf(exp2f((float)i) * p4[q] + 1.5707963267948966f);
            }
        }
        const int i2 = (f < 427) ? f : f - 427;
        const float omega = expf(-9.210340371976184f * (float)i2 / 427.0f);
        const float ang = (float)s * omega;
        v += (f < 427) ? sinf(ang) : cosf(ang);
        orow[f] = v;
    }
}

// ---------------- launch ----------------
extern "C" void kernel_launch(void* const* d_in, const int* in_sizes, int n_in,
                              void* d_out, int out_size)
{
    (void)in_sizes; (void)n_in; (void)out_size;
    const float* fm0    = (const float*)d_in[0];
    const float* fm1    = (const float*)d_in[1];
    const float* fm2    = (const float*)d_in[2];
    const float* coords = (const float*)d_in[3];
    const float* tf0    = (const float*)d_in[4];
    const float* tf1    = (const float*)d_in[5];
    const float* tf2    = (const float*)d_in[6];
    const float* vis    = (const float*)d_in[7];
    const float* conf   = (const float*)d_in[8];
    const float* W1     = (const float*)d_in[9];
    const float* b1     = (const float*)d_in[10];
    const float* W2     = (const float*)d_in[11];
    const float* W2b    = (const float*)d_in[12];
    float* out = (float*)d_out;

    float *fT, *vol, *hbuf, *ebuf, *w1r, *w2r;
    cudaGetSymbolAddress((void**)&fT,   g_fmapT);
    cudaGetSymbolAddress((void**)&vol,  g_vol);
    cudaGetSymbolAddress((void**)&hbuf, g_h);
    cudaGetSymbolAddress((void**)&ebuf, g_emb);
    cudaGetSymbolAddress((void**)&w1r,  g_w1r);
    cudaGetSymbolAddress((void**)&w2r,  g_w2r);

    cudaFuncSetAttribute(vol_kernel, cudaFuncAttributeMaxDynamicSharedMemorySize, VOL_SMEM);

    dim3 tb(32, 8);
    transpose_kernel<<<dim3(3072 / 32, 4, 16), tb>>>(fm0, fT, 3072);
    transpose_kernel<<<dim3(768 / 32, 4, 16),  tb>>>(fm1, fT + FT1_OFF, 768);
    transpose_kernel<<<dim3(192 / 32, 4, 16),  tb>>>(fm2, fT + FT2_OFF, 192);

    round_tf32_kernel<<<(K1 * 384 + 255) / 256, 256>>>(W1, w1r, K1 * 384);
    round_tf32_kernel<<<(384 * 256 + 255) / 256, 256>>>(W2, w2r, 384 * 256);

    vol_kernel<<<dim3(N_, S_, 3), 256, VOL_SMEM>>>(fT, tf0, tf1, tf2, coords, vol);

    tf32_gemm_pipe<true,  true ><<<dim3(3, 96), 256>>>(vol,  VSTR, w1r, 384, b1,  hbuf, 384, VSTR, K1);
    tf32_gemm_pipe<false, false><<<dim3(2, 96), 256>>>(hbuf, 384,  w2r, 256, W2b, ebuf, 256, 384,  384);

    assemble_kernel<<<dim3(N_, S_), 256>>>(ebuf, coords, vis, conf, out);
}

// round 5
// speedup vs baseline: 2.3347x; 1.0676x over previous
#include <cuda_runtime.h>
#include <cuda_bf16.h>
#include <math.h>
#include <stdint.h>

// ---------------- constants ----------------
#define S_   16
#define N_   256
#define D_   128
#define RR   49
#define K1   2401            // 49*49
#define VSTR 2416            // padded vol row stride (mult of 16)
#define ROWS_T 12288         // 3 levels * 16 * 256

// fmapT offsets
#define FT1_OFF 6291456      // 16*48*64*128
#define FT2_OFF 7864320      // + 16*24*32*128

// ---------------- scratch (static device memory; no allocs) ----------------
__device__ float g_fmapT[8257536];           // all 3 transposed fmaps
__device__ float g_vol[ROWS_T * VSTR];       // 12288 x 2416
__device__ float g_h[ROWS_T * 384];
__device__ float g_emb[ROWS_T * 256];
__device__ float g_w1r[K1 * 384];            // tf32-rounded W1
__device__ float g_w2r[384 * 256];           // tf32-rounded W2

// ---------------- helpers ----------------
__device__ __forceinline__ uint32_t f2tf32(float f)
{
    uint32_t r;
    asm("cvt.rna.tf32.f32 %0, %1;" : "=r"(r) : "f"(f));
    return r;
}

__device__ __forceinline__ float tf32r(float f) { return __uint_as_float(f2tf32(f)); }

__device__ __forceinline__ uint32_t pack_bf2(float a, float b)
{
    __nv_bfloat162 p = __floats2bfloat162_rn(a, b);
    return *(uint32_t*)&p;
}

__device__ __forceinline__ void mma_tf32(float* c, const uint32_t* a, const uint32_t* b)
{
    asm volatile(
        "mma.sync.aligned.m16n8k8.row.col.f32.tf32.tf32.f32 "
        "{%0,%1,%2,%3}, {%4,%5,%6,%7}, {%8,%9}, {%0,%1,%2,%3};"
        : "+f"(c[0]), "+f"(c[1]), "+f"(c[2]), "+f"(c[3])
        : "r"(a[0]), "r"(a[1]), "r"(a[2]), "r"(a[3]), "r"(b[0]), "r"(b[1]));
}

__device__ __forceinline__ void mma_bf16(float* c, const uint32_t* a, const uint32_t* b)
{
    asm volatile(
        "mma.sync.aligned.m16n8k16.row.col.f32.bf16.bf16.f32 "
        "{%0,%1,%2,%3}, {%4,%5,%6,%7}, {%8,%9}, {%0,%1,%2,%3};"
        : "+f"(c[0]), "+f"(c[1]), "+f"(c[2]), "+f"(c[3])
        : "r"(a[0]), "r"(a[1]), "r"(a[2]), "r"(a[3]), "r"(b[0]), "r"(b[1]));
}

__device__ __forceinline__ void cpa16(uint32_t dst, const void* src, bool pred)
{
    asm volatile("cp.async.ca.shared.global [%0], [%1], 16, %2;"
                 :: "r"(dst), "l"(src), "r"(pred ? 16 : 0) : "memory");
}
__device__ __forceinline__ void cpa_commit() { asm volatile("cp.async.commit_group;" ::: "memory"); }
__device__ __forceinline__ void cpa_wait0()  { asm volatile("cp.async.wait_group 0;" ::: "memory"); }
__device__ __forceinline__ void cpa_wait1()  { asm volatile("cp.async.wait_group 1;" ::: "memory"); }

// ---------------- transpose [S,D,H,W] -> [S,H*W,D] ----------------
__global__ void transpose_kernel(const float* __restrict__ src,
                                 float* __restrict__ dst, int HW)
{
    __shared__ float tile[32][33];
    int s   = blockIdx.z;
    int hw0 = blockIdx.x * 32;
    int d0  = blockIdx.y * 32;
    int tx  = threadIdx.x;
    for (int i = threadIdx.y; i < 32; i += 8)
        tile[i][tx] = src[(size_t)(s * D_ + d0 + i) * HW + hw0 + tx];
    __syncthreads();
    for (int i = threadIdx.y; i < 32; i += 8)
        dst[(size_t)(s * HW + hw0 + i) * D_ + d0 + tx] = tile[tx][i];
}

// ---------------- round both weight tensors to tf32-representable fp32 -------
__global__ void round2_kernel(const float* __restrict__ W1s, float* __restrict__ w1d, int n1,
                              const float* __restrict__ W2s, float* __restrict__ w2d, int n2)
{
    int i = blockIdx.x * 256 + threadIdx.x;
    if (i < n1) w1d[i] = tf32r(W1s[i]);
    else {
        int j = i - n1;
        if (j < n2) w2d[j] = tf32r(W2s[j]);
    }
}

// ---------------- vol kernel: 8x8 texel patch -> tensor-core C -> bilinear ---
// A (texels): [m=64][kp 0..63] bf16x2 words, stride 68  (m = 8*ty + tx)
// B (tf):     [n=56 pad][kp 0..63] bf16x2 words, stride 68
// C (post-mma): [64][56] floats, reuses the A/B smem region
#define VA_W 68
#define VA_SZ (64 * VA_W)   // 4352 words
#define VB_SZ (56 * VA_W)   // 3808 words
#define VOL_SMEM ((2 * VA_SZ + 2 * VB_SZ) * 4)   // 65280 B

__global__ __launch_bounds__(256)
void vol_kernel(const float* __restrict__ fmTbase,
                const float* __restrict__ tf0,
                const float* __restrict__ tf1,
                const float* __restrict__ tf2,
                const float* __restrict__ coords, float* __restrict__ vol)
{
    extern __shared__ uint32_t smv[];
    uint32_t* AsH = smv;
    uint32_t* AsL = AsH + VA_SZ;
    uint32_t* BsH = AsL + VA_SZ;
    uint32_t* BsL = BsH + VB_SZ;

    const int n = blockIdx.x, s = blockIdx.y, lev = blockIdx.z;
    const int tid = threadIdx.x, lane = tid & 31, wp = tid >> 5;

    int H, W, off;
    float invscale;
    const float* tfs;
    if (lev == 0)      { H = 48; W = 64; off = 0;       invscale = 1.0f;  tfs = tf0; }
    else if (lev == 1) { H = 24; W = 32; off = FT1_OFF; invscale = 0.5f;  tfs = tf1; }
    else               { H = 12; W = 16; off = FT2_OFF; invscale = 0.25f; tfs = tf2; }

    const int sn = s * N_ + n;
    const float cx = coords[sn * 2 + 0] * invscale;
    const float cy = coords[sn * 2 + 1] * invscale;
    const float fxx = floorf(cx), fyy = floorf(cy);
    const int   ix0 = (int)fxx,   iy0 = (int)fyy;
    const float fx = cx - fxx,    fy = cy - fyy;
    const float w00 = (1.f - fx) * (1.f - fy);
    const float w01 = fx * (1.f - fy);
    const float w10 = (1.f - fx) * fy;
    const float w11 = fx * fy;
    const float* base = fmTbase + off + (size_t)s * H * W * D_;

    // gather raw 8x8 texel patch: warp per texel row m; lane owns 4 channels
    #pragma unroll
    for (int m = wp; m < 64; m += 8) {
        const int ty = m >> 3, tx = m & 7;
        const int yy = iy0 + ty - 3, xx = ix0 + tx - 3;
        float4 t = make_float4(0.f, 0.f, 0.f, 0.f);
        if ((yy >= 0) && (yy < H) && (xx >= 0) && (xx < W))
            t = *(const float4*)(base + ((long)yy * W + xx) * D_ + 4 * lane);
        const float h0 = __bfloat162float(__float2bfloat16(t.x));
        const float h1 = __bfloat162float(__float2bfloat16(t.y));
        const float h2 = __bfloat162float(__float2bfloat16(t.z));
        const float h3 = __bfloat162float(__float2bfloat16(t.w));
        uint2 hi = make_uint2(pack_bf2(h0, h1), pack_bf2(h2, h3));
        uint2 lo = make_uint2(pack_bf2(t.x - h0, t.y - h1), pack_bf2(t.z - h2, t.w - h3));
        *(uint2*)&AsH[m * VA_W + 2 * lane] = hi;
        *(uint2*)&AsL[m * VA_W + 2 * lane] = lo;
    }
    // gather tf: warp per ij; lane owns 4 channels
    for (int ij = wp; ij < RR; ij += 8) {
        float4 t = *(const float4*)(tfs + ((long)ij * N_ + n) * D_ + 4 * lane);
        const float h0 = __bfloat162float(__float2bfloat16(t.x));
        const float h1 = __bfloat162float(__float2bfloat16(t.y));
        const float h2 = __bfloat162float(__float2bfloat16(t.z));
        const float h3 = __bfloat162float(__float2bfloat16(t.w));
        uint2 hi = make_uint2(pack_bf2(h0, h1), pack_bf2(h2, h3));
        uint2 lo = make_uint2(pack_bf2(t.x - h0, t.y - h1), pack_bf2(t.z - h2, t.w - h3));
        *(uint2*)&BsH[ij * VA_W + 2 * lane] = hi;
        *(uint2*)&BsL[ij * VA_W + 2 * lane] = lo;
    }
    __syncthreads();

    float* vrow = vol + (size_t)(lev * 4096 + sn) * VSTR;
    if (tid < VSTR - K1) vrow[K1 + tid] = 0.f;

    // mma: warp -> m tile (warp&3)*16, n half (warp>>2); C = texels . tf
    const int wm  = (wp & 3) * 16;
    const int nh  = wp >> 2;
    const int nt0 = nh ? 4 : 0;
    const int ntN = nh ? 3 : 4;
    const int t = lane & 3, g = lane >> 2;

    float acc[4][4];
    #pragma unroll
    for (int i = 0; i < 4; i++)
        #pragma unroll
        for (int q = 0; q < 4; q++) acc[i][q] = 0.f;

    #pragma unroll
    for (int ks = 0; ks < 8; ks++) {
        const int kpb = ks * 8;
        uint32_t ah[4], al[4];
        const int ra = (wm + g) * VA_W + kpb + t;
        const int rb = (wm + g + 8) * VA_W + kpb + t;
        ah[0] = AsH[ra];     ah[1] = AsH[rb];
        ah[2] = AsH[ra + 4]; ah[3] = AsH[rb + 4];
        al[0] = AsL[ra];     al[1] = AsL[rb];
        al[2] = AsL[ra + 4]; al[3] = AsL[rb + 4];
        #pragma unroll
        for (int ni = 0; ni < 4; ni++) {
            if (ni >= ntN) break;
            const int nb = ((nt0 + ni) * 8 + g) * VA_W + kpb + t;
            uint32_t bh[2], bl[2];
            bh[0] = BsH[nb]; bh[1] = BsH[nb + 4];
            bl[0] = BsL[nb]; bl[1] = BsL[nb + 4];
            mma_bf16(acc[ni], ah, bh);
            mma_bf16(acc[ni], ah, bl);
            mma_bf16(acc[ni], al, bh);
        }
    }

    // store C to smem (reuse A/B region), then bilinear-combine in output space
    __syncthreads();
    float* Cs = (float*)smv;    // [64][56]
    #pragma unroll
    for (int ni = 0; ni < 4; ni++) {
        if (ni >= ntN) break;
        const int col0 = (nt0 + ni) * 8 + 2 * t;
        *(float2*)&Cs[(wm + g) * 56 + col0]     = make_float2(acc[ni][0], acc[ni][1]);
        *(float2*)&Cs[(wm + g + 8) * 56 + col0] = make_float2(acc[ni][2], acc[ni][3]);
    }
    __syncthreads();

    for (int idx = tid; idx < K1; idx += 256) {
        const int hw = idx / 49, ij = idx - hw * 49;
        const int h = hw / 7,  w = hw - h * 7;
        const int m00 = h * 8 + w;
        const float v = w00 * Cs[m00 * 56 + ij]
                      + w01 * Cs[(m00 + 1) * 56 + ij]
                      + w10 * Cs[(m00 + 8) * 56 + ij]
                      + w11 * Cs[(m00 + 9) * 56 + ij];
        vrow[idx] = tf32r(v);
    }
}

// ---------------- pipelined tf32 GEMM, 128x128 tile, cp.async 2-stage -------
__device__ __forceinline__ float gelu_exact(float v)
{
    return 0.5f * v * (1.f + erff(v * 0.7071067811865475f));
}

#define AST 20   // A smem word stride per m row (16 k + pad)
#define BST 136  // B smem word stride per k row (128 n + pad)

template <bool GELU, bool ROUND_OUT>
__global__ __launch_bounds__(256)
void tf32_gemm_pipe(const float* __restrict__ A, int lda,
                    const float* __restrict__ B, int ldb,
                    const float* __restrict__ bias,
                    float* __restrict__ C, int ldc,
                    int K, int Kvalid)
{
    __shared__ float As[2][128 * AST];
    __shared__ float Bs[2][16 * BST];

    const int tid  = threadIdx.x;
    const int lane = tid & 31;
    const int warp = tid >> 5;
    const int m0 = blockIdx.y * 128, n0 = blockIdx.x * 128;
    const int wm = (warp >> 2) * 64, wn = (warp & 3) * 32;
    const int t = lane & 3, g = lane >> 2;

    // cp.async assignments: A needs 128 rows x 16 k = 512 float4 = 2/thread
    const int am = tid >> 1, ak = (tid & 1) * 8;       // A: row 0..127, k-base 0/8
    const int bk = tid >> 5, bnc = (tid & 31) * 4;     // B: k-row, col-quad

    uint32_t sA0, sA1, sB0, sB1;
    {
        uint32_t a = (uint32_t)__cvta_generic_to_shared(&As[0][0]);
        sA0 = a + (am * AST + ak) * 4;
        sA1 = sA0 + 128 * AST * 4;
        uint32_t b = (uint32_t)__cvta_generic_to_shared(&Bs[0][0]);
        sB0 = b + (bk * BST + bnc) * 4;
        sB1 = sB0 + 16 * BST * 4;
    }
    const float* gA = A + (size_t)(m0 + am) * lda + ak;
    const float* gB = B + (size_t)bk * ldb + n0 + bnc;

    float acc[4][4][4];
    #pragma unroll
    for (int mi = 0; mi < 4; mi++)
        #pragma unroll
        for (int ni = 0; ni < 4; ni++)
            #pragma unroll
            for (int q = 0; q < 4; q++) acc[mi][ni][q] = 0.f;

    const int NIT = K / 16;
    // prefetch stage 0
    cpa16(sA0,      gA,     true);
    cpa16(sA0 + 16, gA + 4, true);
    cpa16(sB0, gB, bk < Kvalid);
    cpa16(sB0 + 8 * BST * 4, gB + (size_t)8 * ldb, bk + 8 < Kvalid);
    cpa_commit();

    for (int it = 0; it < NIT; it++) {
        const int cur = it & 1;
        if (it + 1 < NIT) {
            const int k0 = (it + 1) * 16;
            const uint32_t dA = cur ? sA0 : sA1;
            const uint32_t dB = cur ? sB0 : sB1;
            cpa16(dA,      gA + k0,     true);
            cpa16(dA + 16, gA + k0 + 4, true);
            cpa16(dB, gB + (size_t)k0 * ldb, k0 + bk < Kvalid);
            cpa16(dB + 8 * BST * 4, gB + (size_t)(k0 + 8) * ldb, k0 + bk + 8 < Kvalid);
            cpa_commit();
            cpa_wait1();
        } else {
            cpa_wait0();
        }
        __syncthreads();

        const float* Ab = As[cur];
        const float* Bb = Bs[cur];
        #pragma unroll
        for (int kb = 0; kb < 16; kb += 8) {
            uint32_t af[4][4], bf[4][2];
            #pragma unroll
            for (int mi = 0; mi < 4; mi++) {
                const int r = (wm + mi * 16 + g) * AST + kb + t;
                af[mi][0] = __float_as_uint(Ab[r]);
                af[mi][1] = __float_as_uint(Ab[r + 8 * AST]);
                af[mi][2] = __float_as_uint(Ab[r + 4]);
                af[mi][3] = __float_as_uint(Ab[r + 8 * AST + 4]);
            }
            #pragma unroll
            for (int ni = 0; ni < 4; ni++) {
                const int cidx = (kb + t) * BST + wn + ni * 8 + g;
                bf[ni][0] = __float_as_uint(Bb[cidx]);
                bf[ni][1] = __float_as_uint(Bb[cidx + 4 * BST]);
            }
            #pragma unroll
            for (int mi = 0; mi < 4; mi++)
                #pragma unroll
                for (int ni = 0; ni < 4; ni++)
                    mma_tf32(acc[mi][ni], af[mi], bf[ni]);
        }
        __syncthreads();
    }

    // epilogue: bias (+gelu) (+tf32 round), write C
    #pragma unroll
    for (int mi = 0; mi < 4; mi++) {
        const int r0 = m0 + wm + mi * 16 + g;
        #pragma unroll
        for (int ni = 0; ni < 4; ni++) {
            const int c0 = n0 + wn + ni * 8 + 2 * t;
            const float bb0 = bias[c0], bb1 = bias[c0 + 1];
            float v0 = acc[mi][ni][0] + bb0;
            float v1 = acc[mi][ni][1] + bb1;
            float v2 = acc[mi][ni][2] + bb0;
            float v3 = acc[mi][ni][3] + bb1;
            if (GELU) {
                v0 = gelu_exact(v0); v1 = gelu_exact(v1);
                v2 = gelu_exact(v2); v3 = gelu_exact(v3);
            }
            if (ROUND_OUT) {
                v0 = tf32r(v0); v1 = tf32r(v1);
                v2 = tf32r(v2); v3 = tf32r(v3);
            }
            *(float2*)(C + (size_t)r0 * ldc + c0)       = make_float2(v0, v1);
            *(float2*)(C + (size_t)(r0 + 8) * ldc + c0) = make_float2(v2, v3);
        }
    }
}

// ---------------- final assembly: concat + posenc + time embedding ----------------
__global__ void assemble_kernel(const float* __restrict__ emb,
                                const float* __restrict__ coords,
                                const float* __restrict__ vis,
                                const float* __restrict__ conf,
                                float* __restrict__ out)
{
    const int n = blockIdx.x, s = blockIdx.y;
    const int sn = s * N_ + n;

    float rfx = 0.f, rfy = 0.f, rbx = 0.f, rby = 0.f;
    const float cx = coords[sn * 2], cy = coords[sn * 2 + 1];
    if (s < S_ - 1) {
        rfx = cx - coords[((s + 1) * N_ + n) * 2];
        rfy = cy - coords[((s + 1) * N_ + n) * 2 + 1];
    }
    if (s > 0) {
        rbx = cx - coords[((s - 1) * N_ + n) * 2];
        rby = cy - coords[((s - 1) * N_ + n) * 2 + 1];
    }
    float p4[4];
    p4[0] = rfx / 64.f;
    p4[1] = rfy / 48.f;
    p4[2] = rbx / 64.f;
    p4[3] = rby / 48.f;

    float* orow = out + (size_t)(n * S_ + s) * 854;
    for (int f = threadIdx.x; f < 854; f += 256) {
        float v;
        if (f == 0)      v = vis[sn];
        else if (f == 1) v = conf[sn];
        else if (f < 770) {
            const int lev = (f - 2) >> 8;
            const int c   = (f - 2) & 255;
            v = emb[((size_t)(lev * 4096 + sn)) * 256 + c];
        } else {
            const int j = f - 770;
            if (j < 4) v = p4[j];
            else if (j < 44) {
                const int i = (j - 4) >> 2, q = (j - 4) & 3;
                v = sinf(exp2f((float)i) * p4[q]);
            } else {
                const int i = (j - 44) >> 2, q = (j - 44) & 3;
                v = sinf(exp2f((float)i) * p4[q] + 1.5707963267948966f);
            }
        }
        const int i2 = (f < 427) ? f : f - 427;
        const float omega = expf(-9.210340371976184f * (float)i2 / 427.0f);
        const float ang = (float)s * omega;
        v += (f < 427) ? sinf(ang) : cosf(ang);
        orow[f] = v;
    }
}

// ---------------- launch ----------------
extern "C" void kernel_launch(void* const* d_in, const int* in_sizes, int n_in,
                              void* d_out, int out_size)
{
    (void)in_sizes; (void)n_in; (void)out_size;
    const float* fm0    = (const float*)d_in[0];
    const float* fm1    = (const float*)d_in[1];
    const float* fm2    = (const float*)d_in[2];
    const float* coords = (const float*)d_in[3];
    const float* tf0    = (const float*)d_in[4];
    const float* tf1    = (const float*)d_in[5];
    const float* tf2    = (const float*)d_in[6];
    const float* vis    = (const float*)d_in[7];
    const float* conf   = (const float*)d_in[8];
    const float* W1     = (const float*)d_in[9];
    const float* b1     = (const float*)d_in[10];
    const float* W2     = (const float*)d_in[11];
    const float* W2b    = (const float*)d_in[12];
    float* out = (float*)d_out;

    float *fT, *vol, *hbuf, *ebuf, *w1r, *w2r;
    cudaGetSymbolAddress((void**)&fT,   g_fmapT);
    cudaGetSymbolAddress((void**)&vol,  g_vol);
    cudaGetSymbolAddress((void**)&hbuf, g_h);
    cudaGetSymbolAddress((void**)&ebuf, g_emb);
    cudaGetSymbolAddress((void**)&w1r,  g_w1r);
    cudaGetSymbolAddress((void**)&w2r,  g_w2r);

    cudaFuncSetAttribute(vol_kernel, cudaFuncAttributeMaxDynamicSharedMemorySize, VOL_SMEM);

    dim3 tb(32, 8);
    transpose_kernel<<<dim3(3072 / 32, 4, 16), tb>>>(fm0, fT, 3072);
    transpose_kernel<<<dim3(768 / 32, 4, 16),  tb>>>(fm1, fT + FT1_OFF, 768);
    transpose_kernel<<<dim3(192 / 32, 4, 16),  tb>>>(fm2, fT + FT2_OFF, 192);

    const int NR = K1 * 384 + 384 * 256;
    round2_kernel<<<(NR + 255) / 256, 256>>>(W1, w1r, K1 * 384, W2, w2r, 384 * 256);

    vol_kernel<<<dim3(N_, S_, 3), 256, VOL_SMEM>>>(fT, tf0, tf1, tf2, coords, vol);

    tf32_gemm_pipe<true,  true ><<<dim3(3, 96), 256>>>(vol,  VSTR, w1r, 384, b1,  hbuf, 384, VSTR, K1);
    tf32_gemm_pipe<false, false><<<dim3(2, 96), 256>>>(hbuf, 384,  w2r, 256, W2b, ebuf, 256, 384,  384);

    assemble_kernel<<<dim3(N_, S_), 256>>>(ebuf, coords, vis, conf, out);
}